// round 8
// baseline (speedup 1.0000x reference)
#include <cuda_runtime.h>
#include <math.h>

#define BATCH 8
#define NPTS  2048
#define QCOLS 512             // columns per block (quarter split)
#define NQ    4
#define LOG2E 1.4426950408889634f
#define LN2   0.6931471805599453f
#define TPB   128
#define CHUNK 16

// dual potentials, double-buffered: [buf][s: f_ba,g_ab,f_aa,g_bb][b*NPTS + i]
__device__ float g_dual[2][4][BATCH * NPTS];
// per-quarter partial LSE state (log2 domain): [quarter][s][b*NPTS + r]
__device__ float g_pm[NQ][4][BATCH * NPTS];
__device__ float g_ps[NQ][4][BATCH * NPTS];
// 0.5*|p|^2 per point, [0]=x rows, [1]=y rows
__device__ float g_sq[2][BATCH * NPTS];

__device__ __forceinline__ float ex2(float x) {
    float r;
    asm("ex2.approx.ftz.f32 %0, %1;" : "=f"(r) : "f"(x));
    return r;
}
__device__ __forceinline__ unsigned long long pk2(float a, float b) {
    unsigned long long u;
    asm("mov.b64 %0, {%1,%2};" : "=l"(u) : "f"(a), "f"(b));
    return u;
}
__device__ __forceinline__ void upk2(unsigned long long u, float& a, float& b) {
    asm("mov.b64 {%0,%1}, %2;" : "=f"(a), "=f"(b) : "l"(u));
}
__device__ __forceinline__ unsigned long long fma2(unsigned long long a,
                                                   unsigned long long b,
                                                   unsigned long long c) {
    unsigned long long d;
    asm("fma.rn.f32x2 %0, %1, %2, %3;" : "=l"(d) : "l"(a), "l"(b), "l"(c));
    return d;
}

// softmin(eps,C,h)_i = -eps * LSE_j( h_j - C_ij/eps ), C_ij = .5|r_i|^2+.5|c_j|^2 - r.c
// log2 domain: arg2_j = (h_j - .5|c_j|^2/eps)*log2e + r_i.c_j*(log2e/eps)
// The running chunk-max is REQUIRED: the row term .5|r|^2/eps is factored out of
// the LSE, so raw args reach +hundreds of log2 at small eps (round-7 NaN lesson).
// This kernel writes PARTIAL (max, shifted-sum) over a 512-column quarter.
__global__ __launch_bounds__(TPB) void sinkhorn_phase(
    const float* __restrict__ x, const float* __restrict__ y,
    float eps, float dual_scale, int rbuf)
{
    const int s = blockIdx.y;
    const int b = blockIdx.z;
    const int q      = blockIdx.x & 3;
    const int rowblk = blockIdx.x >> 2;
    const float* rows = (s == 0 || s == 2) ? x : y;
    const float* cols = (s == 0 || s == 3) ? y : x;
    const int di = (s == 0) ? 1 : (s == 1) ? 0 : s;
    const float* dual = g_dual[rbuf][di] + b * NPTS;

    // pair-interleaved column table for packed FFMA2:
    // sh[2p]   = (c0a*sc, c0b*sc, c1a*sc, c1b*sc)
    // sh[2p+1] = (c2a*sc, c2b*sc, wa,     wb)      for columns (2p, 2p+1)
    __shared__ float4 sh[QCOLS];

    const float inv_eps = 1.0f / eps;
    const float sc = inv_eps * LOG2E;
    const float logw = -logf((float)NPTS);
    const int col0 = q * QCOLS;

    for (int p = threadIdx.x; p < QCOLS / 2; p += TPB) {
        int j = col0 + 2 * p;
        const float* c = cols + (b * NPTS + j) * 3;
        float c0a = c[0], c1a = c[1], c2a = c[2];
        float c0b = c[3], c1b = c[4], c2b = c[5];
        float ha = logw + dual_scale * dual[j] * inv_eps;
        float hb = logw + dual_scale * dual[j + 1] * inv_eps;
        float wa = (ha - 0.5f * (c0a * c0a + c1a * c1a + c2a * c2a) * inv_eps) * LOG2E;
        float wb = (hb - 0.5f * (c0b * c0b + c1b * c1b + c2b * c2b) * inv_eps) * LOG2E;
        sh[2 * p]     = make_float4(c0a * sc, c0b * sc, c1a * sc, c1b * sc);
        sh[2 * p + 1] = make_float4(c2a * sc, c2b * sc, wa, wb);
    }
    __syncthreads();

    const int r = rowblk * TPB + threadIdx.x;
    const float* xr = rows + (b * NPTS + r) * 3;
    const float x0 = xr[0], x1 = xr[1], x2 = xr[2];
    const unsigned long long X0 = pk2(x0, x0);
    const unsigned long long X1 = pk2(x1, x1);
    const unsigned long long X2 = pk2(x2, x2);

    const ulonglong2* shu = (const ulonglong2*)sh;

    float m = -INFINITY;
    float ssum = 0.0f;

    #pragma unroll 1
    for (int j = 0; j < QCOLS; j += CHUNK) {
        // packed dot products: 3 FFMA2 per column pair (w folded into accumulator)
        unsigned long long d[CHUNK / 2];
        #pragma unroll
        for (int k = 0; k < CHUNK / 2; k++) {
            ulonglong2 A = shu[j + 2 * k];
            ulonglong2 B = shu[j + 2 * k + 1];
            d[k] = fma2(X0, A.x, fma2(X1, A.y, fma2(X2, B.x, B.y)));
        }
        float a[CHUNK];
        #pragma unroll
        for (int k = 0; k < CHUNK / 2; k++) upk2(d[k], a[2 * k], a[2 * k + 1]);

        // chunk-local max tree
        float t0 = fmaxf(a[0], a[1]),   t1 = fmaxf(a[2], a[3]);
        float t2 = fmaxf(a[4], a[5]),   t3 = fmaxf(a[6], a[7]);
        float t4 = fmaxf(a[8], a[9]),   t5 = fmaxf(a[10], a[11]);
        float t6 = fmaxf(a[12], a[13]), t7 = fmaxf(a[14], a[15]);
        float u0 = fmaxf(t0, t1), u1 = fmaxf(t2, t3);
        float u2 = fmaxf(t4, t5), u3 = fmaxf(t6, t7);
        float cm = fmaxf(fmaxf(u0, u1), fmaxf(u2, u3));

        // exps relative to chunk max (independent across chunks -> pipelines)
        float e[CHUNK];
        #pragma unroll
        for (int k = 0; k < CHUNK; k++) e[k] = ex2(a[k] - cm);
        float s0 = (e[0] + e[1]) + (e[2] + e[3]);
        float s1 = (e[4] + e[5]) + (e[6] + e[7]);
        float s2 = (e[8] + e[9]) + (e[10] + e[11]);
        float s3 = (e[12] + e[13]) + (e[14] + e[15]);
        float csum = (s0 + s1) + (s2 + s3);

        // branchless merge
        float mn = fmaxf(m, cm);
        ssum = fmaf(ssum, ex2(m - mn), csum * ex2(cm - mn));
        m = mn;
    }

    g_pm[q][s][b * NPTS + r] = m;
    g_ps[q][s][b * NPTS + r] = ssum;
}

// merge the four column-quarters, finish the softmin, apply averaging
__global__ void sinkhorn_combine(float eps, int do_avg, int rbuf, int wbuf)
{
    int idx = blockIdx.x * 256 + threadIdx.x;      // 4*BATCH*NPTS = 65536
    int s = idx >> 14;
    int rem = idx & 16383;                         // b*NPTS + r
    float m0 = g_pm[0][s][rem], m1 = g_pm[1][s][rem];
    float m2 = g_pm[2][s][rem], m3 = g_pm[3][s][rem];
    float s0 = g_ps[0][s][rem], s1 = g_ps[1][s][rem];
    float s2 = g_ps[2][s][rem], s3 = g_ps[3][s][rem];
    float mn = fmaxf(fmaxf(m0, m1), fmaxf(m2, m3));
    float sm = fmaf(s0, ex2(m0 - mn), s1 * ex2(m1 - mn))
             + fmaf(s2, ex2(m2 - mn), s3 * ex2(m3 - mn));
    float lse = LN2 * (mn + log2f(sm));
    int rows_sel = (s == 0 || s == 2) ? 0 : 1;
    float fraw = -eps * lse + g_sq[rows_sel][rem];
    float o = do_avg ? 0.5f * (g_dual[rbuf][s][rem] + fraw) : fraw;
    g_dual[wbuf][s][rem] = o;
}

__global__ void init_sq(const float* __restrict__ x, const float* __restrict__ y)
{
    int idx = blockIdx.x * 256 + threadIdx.x;      // 2*BATCH*NPTS = 32768
    int sel = idx >> 14;
    int rem = idx & 16383;
    const float* p = (sel ? y : x) + rem * 3;
    g_sq[sel][rem] = 0.5f * (p[0] * p[0] + p[1] * p[1] + p[2] * p[2]);
}

// out[b] = (1/N) * sum_i (f_ba - f_aa) + (1/M) * sum_j (g_ab - g_bb)
__global__ void sinkhorn_reduce(float* __restrict__ out, int buf)
{
    const int b = blockIdx.x;
    const int tid = threadIdx.x;
    float acc = 0.0f;
    for (int i = tid; i < NPTS; i += 256) {
        acc += g_dual[buf][0][b * NPTS + i] - g_dual[buf][2][b * NPTS + i];
        acc += g_dual[buf][1][b * NPTS + i] - g_dual[buf][3][b * NPTS + i];
    }
    __shared__ float red[256];
    red[tid] = acc;
    __syncthreads();
    for (int off = 128; off > 0; off >>= 1) {
        if (tid < off) red[tid] += red[tid + off];
        __syncthreads();
    }
    if (tid == 0) {
        float w = expf(-logf((float)NPTS));
        out[b] = red[0] * w;
    }
}

extern "C" void kernel_launch(void* const* d_in, const int* in_sizes, int n_in,
                              void* d_out, int out_size)
{
    const float* x = (const float*)d_in[0];
    const float* y = (const float*)d_in[1];
    float* out = (float*)d_out;

    dim3 grid(NQ * NPTS / TPB, 4, BATCH);   // (64, 4, 8) = 2048 blocks

    // epsilon schedule: [diameter^2] + exp(arange(2ln2, 2ln0.05, 2ln0.5)) + [blur^2]
    const float eps_list[8] = {4.0f, 4.0f, 1.0f, 0.25f, 0.0625f,
                               0.015625f, 0.00390625f, 0.0025f};

    init_sq<<<128, 256>>>(x, y);

    // init at eps0=4 (h = log-weights only) -> buf0
    sinkhorn_phase<<<grid, TPB>>>(x, y, 4.0f, 0.0f, 0);
    sinkhorn_combine<<<256, 256>>>(4.0f, 0, 0, 0);

    int cur = 0;
    for (int i = 0; i < 8; i++) {
        sinkhorn_phase<<<grid, TPB>>>(x, y, eps_list[i], 1.0f, cur);
        sinkhorn_combine<<<256, 256>>>(eps_list[i], 1, cur, cur ^ 1);
        cur ^= 1;
    }
    // final extrapolation at blur^2, no averaging
    sinkhorn_phase<<<grid, TPB>>>(x, y, 0.0025f, 1.0f, cur);
    sinkhorn_combine<<<256, 256>>>(0.0025f, 0, cur, cur ^ 1);
    cur ^= 1;

    sinkhorn_reduce<<<BATCH, 256>>>(out, cur);
}

// round 9
// speedup vs baseline: 1.1230x; 1.1230x over previous
#include <cuda_runtime.h>
#include <math.h>

#define BATCH 8
#define NPTS  2048
#define HCOLS 1024            // columns per block (half split)
#define LOG2E 1.4426950408889634f
#define LN2   0.6931471805599453f
#define TPB   128
#define CHUNK 16

// dual potentials, double-buffered: [buf][s: f_ba,g_ab,f_aa,g_bb][b*NPTS + i]
__device__ float g_dual[2][4][BATCH * NPTS];
// per-half PLAIN partial sums (shifted log2 domain): [half][s][b*NPTS + r]
__device__ float g_ps[2][4][BATCH * NPTS];
// 0.5*|p|^2 per point, [0]=x rows, [1]=y rows
__device__ float g_sq[2][BATCH * NPTS];

__device__ __forceinline__ float ex2(float x) {
    float r;
    asm("ex2.approx.ftz.f32 %0, %1;" : "=f"(r) : "f"(x));
    return r;
}
__device__ __forceinline__ unsigned long long pk2(float a, float b) {
    unsigned long long u;
    asm("mov.b64 %0, {%1,%2};" : "=l"(u) : "f"(a), "f"(b));
    return u;
}
__device__ __forceinline__ void upk2(unsigned long long u, float& a, float& b) {
    asm("mov.b64 {%0,%1}, %2;" : "=f"(a), "=f"(b) : "l"(u));
}
__device__ __forceinline__ unsigned long long fma2(unsigned long long a,
                                                   unsigned long long b,
                                                   unsigned long long c) {
    unsigned long long d;
    asm("fma.rn.f32x2 %0, %1, %2, %3;" : "=l"(d) : "l"(a), "l"(b), "l"(c));
    return d;
}
__device__ __forceinline__ unsigned long long add2(unsigned long long a,
                                                   unsigned long long b) {
    unsigned long long d;
    asm("add.rn.f32x2 %0, %1, %2;" : "=l"(d) : "l"(a), "l"(b));
    return d;
}

// softmin(eps,C,h)_i = -eps * LSE_j( h_j - C_ij/eps ), C_ij = .5|r_i|^2+.5|c_j|^2 - r.c
// log2 domain, PER-ROW SHIFT instead of online max:
//   S_i = (0.5|r_i|^2 - f_prev_i) * log2e / eps   (estimate of the row's log2-LSE)
//   ssum_i = sum_j 2^(arg_ij - S_i)   -- bounded since f drifts << 115*eps*ln2/phase
//   f_new_i = f_prev_i - eps*ln2*log2(ssum_i)
// Init phase (shift=0, eps=4): raw args lie in [-11.5,-10.7] log2 -> safe unshifted.
__global__ __launch_bounds__(TPB) void sinkhorn_phase(
    const float* __restrict__ x, const float* __restrict__ y,
    float eps, float dual_scale, int shift, int rbuf)
{
    const int s = blockIdx.y;
    const int b = blockIdx.z;
    const int half   = blockIdx.x & 1;
    const int rowblk = blockIdx.x >> 1;
    const float* rows = (s == 0 || s == 2) ? x : y;
    const float* cols = (s == 0 || s == 3) ? y : x;
    const int di = (s == 0) ? 1 : (s == 1) ? 0 : s;
    const float* dual = g_dual[rbuf][di] + b * NPTS;
    const float* own  = g_dual[rbuf][s]  + b * NPTS;

    // pair-interleaved column table for packed FFMA2:
    // sh[2p]   = (c0a*sc, c0b*sc, c1a*sc, c1b*sc)
    // sh[2p+1] = (c2a*sc, c2b*sc, wa,     wb)      for columns (2p, 2p+1)
    __shared__ float4 sh[HCOLS];

    const float inv_eps = 1.0f / eps;
    const float sc = inv_eps * LOG2E;
    const float logw = -logf((float)NPTS);
    const int col0 = half * HCOLS;

    for (int p = threadIdx.x; p < HCOLS / 2; p += TPB) {
        int j = col0 + 2 * p;
        const float* c = cols + (b * NPTS + j) * 3;
        float c0a = c[0], c1a = c[1], c2a = c[2];
        float c0b = c[3], c1b = c[4], c2b = c[5];
        float ha = logw + dual_scale * dual[j] * inv_eps;
        float hb = logw + dual_scale * dual[j + 1] * inv_eps;
        float wa = (ha - 0.5f * (c0a * c0a + c1a * c1a + c2a * c2a) * inv_eps) * LOG2E;
        float wb = (hb - 0.5f * (c0b * c0b + c1b * c1b + c2b * c2b) * inv_eps) * LOG2E;
        sh[2 * p]     = make_float4(c0a * sc, c0b * sc, c1a * sc, c1b * sc);
        sh[2 * p + 1] = make_float4(c2a * sc, c2b * sc, wa, wb);
    }
    __syncthreads();

    const int r = rowblk * TPB + threadIdx.x;
    const float* xr = rows + (b * NPTS + r) * 3;
    const float x0 = xr[0], x1 = xr[1], x2 = xr[2];
    const unsigned long long X0 = pk2(x0, x0);
    const unsigned long long X1 = pk2(x1, x1);
    const unsigned long long X2 = pk2(x2, x2);

    // per-row shift from previous dual value (always finite: zero-init / prior phase)
    const float sqr = 0.5f * (x0 * x0 + x1 * x1 + x2 * x2);
    const float S = shift ? (sqr - own[r]) * inv_eps * LOG2E : 0.0f;
    const unsigned long long nS2 = pk2(-S, -S);

    const ulonglong2* shu = (const ulonglong2*)sh;

    float ssum = 0.0f;

    #pragma unroll 1
    for (int j = 0; j < HCOLS; j += CHUNK) {
        // packed dots with w and -S folded in: 3 FFMA2 + 1 FADD2 per column pair
        unsigned long long d[CHUNK / 2];
        #pragma unroll
        for (int k = 0; k < CHUNK / 2; k++) {
            ulonglong2 A = shu[j + 2 * k];
            ulonglong2 B = shu[j + 2 * k + 1];
            d[k] = fma2(X0, A.x, fma2(X1, A.y, fma2(X2, B.x, add2(B.y, nS2))));
        }
        float a[CHUNK];
        #pragma unroll
        for (int k = 0; k < CHUNK / 2; k++) upk2(d[k], a[2 * k], a[2 * k + 1]);

        // 16 independent ex2 at the MUFU floor; no max, no merge
        float e[CHUNK];
        #pragma unroll
        for (int k = 0; k < CHUNK; k++) e[k] = ex2(a[k]);
        float s0 = (e[0] + e[1]) + (e[2] + e[3]);
        float s1 = (e[4] + e[5]) + (e[6] + e[7]);
        float s2 = (e[8] + e[9]) + (e[10] + e[11]);
        float s3 = (e[12] + e[13]) + (e[14] + e[15]);
        ssum += (s0 + s1) + (s2 + s3);
    }

    g_ps[half][s][b * NPTS + r] = ssum;
}

// merge the two halves, finish the softmin, apply averaging
__global__ void sinkhorn_combine(float eps, int do_avg, int shift, int rbuf, int wbuf)
{
    int idx = blockIdx.x * 256 + threadIdx.x;      // 4*BATCH*NPTS = 65536
    int s = idx >> 14;
    int rem = idx & 16383;                         // b*NPTS + r
    float sm = g_ps[0][s][rem] + g_ps[1][s][rem];
    float l2 = log2f(sm);
    float fp = g_dual[rbuf][s][rem];
    int rows_sel = (s == 0 || s == 2) ? 0 : 1;
    float fraw = shift ? fp - eps * LN2 * l2
                       : g_sq[rows_sel][rem] - eps * LN2 * l2;
    float o = do_avg ? 0.5f * (fp + fraw) : fraw;
    g_dual[wbuf][s][rem] = o;
}

__global__ void init_sq(const float* __restrict__ x, const float* __restrict__ y)
{
    int idx = blockIdx.x * 256 + threadIdx.x;      // 2*BATCH*NPTS = 32768
    int sel = idx >> 14;
    int rem = idx & 16383;
    const float* p = (sel ? y : x) + rem * 3;
    g_sq[sel][rem] = 0.5f * (p[0] * p[0] + p[1] * p[1] + p[2] * p[2]);
}

// out[b] = (1/N) * sum_i (f_ba - f_aa) + (1/M) * sum_j (g_ab - g_bb)
__global__ void sinkhorn_reduce(float* __restrict__ out, int buf)
{
    const int b = blockIdx.x;
    const int tid = threadIdx.x;
    float acc = 0.0f;
    for (int i = tid; i < NPTS; i += 256) {
        acc += g_dual[buf][0][b * NPTS + i] - g_dual[buf][2][b * NPTS + i];
        acc += g_dual[buf][1][b * NPTS + i] - g_dual[buf][3][b * NPTS + i];
    }
    __shared__ float red[256];
    red[tid] = acc;
    __syncthreads();
    for (int off = 128; off > 0; off >>= 1) {
        if (tid < off) red[tid] += red[tid + off];
        __syncthreads();
    }
    if (tid == 0) {
        float w = expf(-logf((float)NPTS));
        out[b] = red[0] * w;
    }
}

extern "C" void kernel_launch(void* const* d_in, const int* in_sizes, int n_in,
                              void* d_out, int out_size)
{
    const float* x = (const float*)d_in[0];
    const float* y = (const float*)d_in[1];
    float* out = (float*)d_out;

    dim3 grid(2 * NPTS / TPB, 4, BATCH);   // (32, 4, 8) = 1024 blocks

    // epsilon schedule: [diameter^2] + exp(arange(2ln2, 2ln0.05, 2ln0.5)) + [blur^2]
    const float eps_list[8] = {4.0f, 4.0f, 1.0f, 0.25f, 0.0625f,
                               0.015625f, 0.00390625f, 0.0025f};

    init_sq<<<128, 256>>>(x, y);

    // init at eps0=4 (h = log-weights only, no shift) -> buf0
    sinkhorn_phase<<<grid, TPB>>>(x, y, 4.0f, 0.0f, 0, 0);
    sinkhorn_combine<<<256, 256>>>(4.0f, 0, 0, 0, 0);

    int cur = 0;
    for (int i = 0; i < 8; i++) {
        sinkhorn_phase<<<grid, TPB>>>(x, y, eps_list[i], 1.0f, 1, cur);
        sinkhorn_combine<<<256, 256>>>(eps_list[i], 1, 1, cur, cur ^ 1);
        cur ^= 1;
    }
    // final extrapolation at blur^2, no averaging
    sinkhorn_phase<<<grid, TPB>>>(x, y, 0.0025f, 1.0f, 1, cur);
    sinkhorn_combine<<<256, 256>>>(0.0025f, 0, 1, cur, cur ^ 1);
    cur ^= 1;

    sinkhorn_reduce<<<BATCH, 256>>>(out, cur);
}